// round 9
// baseline (speedup 1.0000x reference)
#include <cuda_runtime.h>
#include <cstdint>

// Centroids: out[n] = argmin_c ( |c|^2 - 2 * latent[n].coords[c] )
// Broadcast-B FFMA2 design:
//   1 latent row per thread, fully register-resident (64 packed f32x2).
//   Coord tile (128 centroids) in smem; every warp reads centroid rows as
//   pure broadcast LDS (16B crossbar per LDS.128 instead of 512B).
//   Per centroid: 32 LDS.128 + 64 FFMA2 + 5-op fold  ->  fma-pipe bound.
// Output: float32 indices (established R6).

#define THREADS 256
#define TILE_C  128
#define DIM     128

__device__ float g_c2[4096];   // |c|^2 per centroid

__device__ __forceinline__ unsigned long long ffma2(unsigned long long a,
                                                    unsigned long long b,
                                                    unsigned long long c) {
    unsigned long long d;
    asm("fma.rn.f32x2 %0, %1, %2, %3;" : "=l"(d) : "l"(a), "l"(b), "l"(c));
    return d;
}
__device__ __forceinline__ unsigned long long addf2(unsigned long long a,
                                                    unsigned long long b) {
    unsigned long long d;
    asm("add.rn.f32x2 %0, %1, %2;" : "=l"(d) : "l"(a), "l"(b));
    return d;
}
__device__ __forceinline__ float2 unpack_f32x2(unsigned long long v) {
    float2 f;
    asm("mov.b64 {%0, %1}, %2;" : "=f"(f.x), "=f"(f.y) : "l"(v));
    return f;
}

// ---- pass 1: |c|^2, one warp per centroid ----
__global__ void c2_kernel(const float* __restrict__ coords, int n_cent) {
    int c    = blockIdx.x * 8 + (threadIdx.x >> 5);
    int lane = threadIdx.x & 31;
    if (c >= n_cent) return;
    const float4* p = reinterpret_cast<const float4*>(coords + (size_t)c * DIM);
    float4 v = p[lane];
    float s = v.x * v.x + v.y * v.y + v.z * v.z + v.w * v.w;
    #pragma unroll
    for (int off = 16; off > 0; off >>= 1)
        s += __shfl_xor_sync(0xffffffffu, s, off);
    if (lane == 0) g_c2[c] = s;
}

// ---- pass 2: broadcast-B FFMA2 GEMM + running argmin ----
__global__ void __launch_bounds__(THREADS, 1)
centroids_argmin_kernel(const float* __restrict__ latent,
                        const float* __restrict__ coords,
                        float* __restrict__ out,
                        int n_rows, int n_cent)
{
    extern __shared__ float sm[];
    float* s_c  = sm;                 // [TILE_C * DIM]  64 KB
    float* s_c2 = sm + TILE_C * DIM;  // [TILE_C]

    const int tid  = threadIdx.x;
    const int row  = blockIdx.x * THREADS + tid;
    const int rowc = row < n_rows ? row : (n_rows - 1);

    // Full latent row in registers as 64 packed f32x2.
    unsigned long long xr[DIM / 2];
    {
        const unsigned long long* xp =
            reinterpret_cast<const unsigned long long*>(latent + (size_t)rowc * DIM);
        #pragma unroll
        for (int i = 0; i < DIM / 2; i++) xr[i] = xp[i];
    }

    float best    = 3.402823466e38f;
    int   bestIdx = 0;

    for (int t0 = 0; t0 < n_cent; t0 += TILE_C) {
        __syncthreads();   // previous-tile reads complete before overwrite

        // Cooperative tile load: 128 rows * 32 float4 = 4096 float4.
        {
            const float4* g = reinterpret_cast<const float4*>(coords + (size_t)t0 * DIM);
            float4*       s = reinterpret_cast<float4*>(s_c);
            #pragma unroll
            for (int k = 0; k < (TILE_C * DIM / 4) / THREADS; k++)
                s[tid + k * THREADS] = g[tid + k * THREADS];
        }
        if (tid < TILE_C) s_c2[tid] = g_c2[t0 + tid];
        __syncthreads();

        // Score all centroids in the tile. Broadcast LDS of centroid rows.
        #pragma unroll 2
        for (int c = 0; c < TILE_C; c++) {
            const ulonglong2* cp =
                reinterpret_cast<const ulonglong2*>(s_c + c * DIM);
            unsigned long long a0 = 0ull, a1 = 0ull, a2 = 0ull, a3 = 0ull;
            #pragma unroll
            for (int i = 0; i < 32; i += 2) {
                ulonglong2 b0 = cp[i];
                ulonglong2 b1 = cp[i + 1];
                a0 = ffma2(xr[2 * i + 0], b0.x, a0);
                a1 = ffma2(xr[2 * i + 1], b0.y, a1);
                a2 = ffma2(xr[2 * i + 2], b1.x, a2);
                a3 = ffma2(xr[2 * i + 3], b1.y, a3);
            }
            unsigned long long s01 = addf2(a0, a1);
            unsigned long long s23 = addf2(a2, a3);
            float2 f = unpack_f32x2(addf2(s01, s23));
            float dot   = f.x + f.y;
            float score = fmaf(-2.0f, dot, s_c2[c]);
            if (score < best) { best = score; bestIdx = t0 + c; }
        }
    }

    if (row < n_rows) out[row] = (float)bestIdx;
}

extern "C" void kernel_launch(void* const* d_in, const int* in_sizes, int n_in,
                              void* d_out, int out_size)
{
    // Inputs by size: latent (131072x128) larger than coords (2048x128).
    int i_lat = 0, i_crd = 1;
    if (n_in >= 2 && in_sizes[1] > in_sizes[0]) { i_lat = 1; i_crd = 0; }

    const float* latent = (const float*)d_in[i_lat];
    const float* coords = (const float*)d_in[i_crd];

    int n_rows_a = out_size;
    int n_rows_b = in_sizes[i_lat] / DIM;
    int n_rows = n_rows_a < n_rows_b ? n_rows_a : n_rows_b;
    int n_cent = in_sizes[i_crd] / DIM;       // 2048
    float* out = (float*)d_out;

    size_t smem = (TILE_C * DIM + TILE_C) * sizeof(float);   // ~64.5 KB

    static bool attr_set = false;
    if (!attr_set) {
        cudaFuncSetAttribute(centroids_argmin_kernel,
                             cudaFuncAttributeMaxDynamicSharedMemorySize,
                             (int)smem);
        attr_set = true;
    }

    c2_kernel<<<(n_cent + 7) / 8, 256>>>(coords, n_cent);

    dim3 grid((n_rows + THREADS - 1) / THREADS);
    centroids_argmin_kernel<<<grid, THREADS, smem>>>(latent, coords, out,
                                                     n_rows, n_cent);
}

// round 10
// speedup vs baseline: 1.2811x; 1.2811x over previous
#include <cuda_runtime.h>
#include <cstdint>

// Centroids: out[n] = argmin_c ( |c|^2 - 2 * latent[n].coords[c] )
// 8x8 register micro-tile, mixed smem addressing:
//   lanes -> rows   (A LDS.128 distinct, conflict-free via 132-stride pad)
//   warps -> cents  (B LDS.128 warp-uniform broadcast, ~2 L1-cyc)
// CTA tile: 256 rows x 64 centroids; A resident (132KB), B double-buffered.
// Per k-quad/warp: L1 ~48 cyc vs fma 64 cyc  ->  fma-pipe bound.
// Output: float32 indices (established R6).

#define THREADS  256
#define CTA_M    256
#define TILE_N   64
#define DIM      128
#define AS       132              // padded A stride (floats)
#define BS       132              // padded B stride (floats)

#define SM_A     0                           // 256*132 floats
#define SM_B(b)  (CTA_M * AS + (b) * TILE_N * BS)
#define SM_C2(b) (CTA_M * AS + 2 * TILE_N * BS + (b) * TILE_N)
#define SM_RED   SM_B(0)                     // reuse B for final reduce
#define SMEM_FLOATS (CTA_M * AS + 2 * TILE_N * BS + 2 * TILE_N)

__device__ float g_c2[4096];   // |c|^2 per centroid

__device__ __forceinline__ unsigned long long ffma2(unsigned long long a,
                                                    unsigned long long b,
                                                    unsigned long long c) {
    unsigned long long d;
    asm("fma.rn.f32x2 %0, %1, %2, %3;" : "=l"(d) : "l"(a), "l"(b), "l"(c));
    return d;
}
__device__ __forceinline__ float2 unpack_f32x2(unsigned long long v) {
    float2 f;
    asm("mov.b64 {%0, %1}, %2;" : "=f"(f.x), "=f"(f.y) : "l"(v));
    return f;
}

// ---- pass 1: |c|^2, one warp per centroid ----
__global__ void c2_kernel(const float* __restrict__ coords, int n_cent) {
    int c    = blockIdx.x * 8 + (threadIdx.x >> 5);
    int lane = threadIdx.x & 31;
    if (c >= n_cent) return;
    const float4* p = reinterpret_cast<const float4*>(coords + (size_t)c * DIM);
    float4 v = p[lane];
    float s = v.x * v.x + v.y * v.y + v.z * v.z + v.w * v.w;
    #pragma unroll
    for (int off = 16; off > 0; off >>= 1)
        s += __shfl_xor_sync(0xffffffffu, s, off);
    if (lane == 0) g_c2[c] = s;
}

// ---- pass 2: 8x8 micro-tile FFMA2 GEMM + argmin ----
__global__ void __launch_bounds__(THREADS, 1)
centroids_argmin_kernel(const float* __restrict__ latent,
                        const float* __restrict__ coords,
                        float* __restrict__ out,
                        int n_rows, int n_cent)
{
    extern __shared__ float sm[];

    const int tid  = threadIdx.x;
    const int lane = tid & 31;
    const int w    = tid >> 5;          // warp 0..7 -> centroid slice
    const int rowBase = blockIdx.x * CTA_M;
    const int n_tiles = n_cent / TILE_N;

    // ---- A tile: 256 rows x 128 k (padded stride) ----
    {
        const float4* g = reinterpret_cast<const float4*>(latent);
        #pragma unroll
        for (int t = tid; t < CTA_M * 32; t += THREADS) {
            int r  = t >> 5;
            int kq = t & 31;
            int gr = rowBase + r; if (gr >= n_rows) gr = n_rows - 1;
            *reinterpret_cast<float4*>(sm + SM_A + r * AS + kq * 4) =
                g[(size_t)gr * 32 + kq];
        }
    }

    const float4* crd4 = reinterpret_cast<const float4*>(coords);
    auto loadB = [&](int nbt) {
        int buf = nbt & 1;
        #pragma unroll
        for (int t = tid; t < TILE_N * 32; t += THREADS) {
            int r  = t >> 5;
            int kq = t & 31;
            int gc = nbt * TILE_N + r; if (gc >= n_cent) gc = n_cent - 1;
            *reinterpret_cast<float4*>(sm + SM_B(buf) + r * BS + kq * 4) =
                crd4[(size_t)gc * 32 + kq];
        }
        if (tid < TILE_N) {
            int gc = nbt * TILE_N + tid; if (gc >= n_cent) gc = n_cent - 1;
            sm[SM_C2(buf) + tid] = g_c2[gc];
        }
    };

    float best[8];
    int   bidx[8];
    #pragma unroll
    for (int j = 0; j < 8; j++) { best[j] = 3.402823466e38f; bidx[j] = 0; }

    loadB(0);
    __syncthreads();

    for (int nb = 0; nb < n_tiles; nb++) {
        int cur = nb & 1;
        if (nb + 1 < n_tiles) loadB(nb + 1);

        const float* Bb = sm + SM_B(cur) + (w * 8) * BS;

        unsigned long long acc[8][8];
        #pragma unroll
        for (int j = 0; j < 8; j++)
            #pragma unroll
            for (int i = 0; i < 8; i++) acc[j][i] = 0ull;

        #pragma unroll 2
        for (int kq = 0; kq < 32; kq++) {
            ulonglong2 b[8];
            #pragma unroll
            for (int i = 0; i < 8; i++)      // warp-uniform -> broadcast LDS
                b[i] = *reinterpret_cast<const ulonglong2*>(Bb + i * BS + kq * 4);
            #pragma unroll
            for (int j = 0; j < 8; j++) {
                ulonglong2 a = *reinterpret_cast<const ulonglong2*>(
                    sm + SM_A + (lane + 32 * j) * AS + kq * 4);
                #pragma unroll
                for (int i = 0; i < 8; i++)
                    acc[j][i] = ffma2(a.y, b[i].y, ffma2(a.x, b[i].x, acc[j][i]));
            }
        }

        // Fold + running argmin for this thread's 8 rows x 8 cents.
        const float* c2s = sm + SM_C2(cur) + w * 8;
        #pragma unroll
        for (int j = 0; j < 8; j++)
            #pragma unroll
            for (int i = 0; i < 8; i++) {
                float2 f = unpack_f32x2(acc[j][i]);
                float score = fmaf(-2.0f, f.x + f.y, c2s[i]);
                if (score < best[j]) { best[j] = score; bidx[j] = nb * TILE_N + w * 8 + i; }
            }

        __syncthreads();   // compute done + next-B loaded before buffer reuse
    }

    // ---- cross-warp reduction: row (lane+32j) best over 8 warps ----
    float2* red = reinterpret_cast<float2*>(sm + SM_RED);   // [256][8]
    #pragma unroll
    for (int j = 0; j < 8; j++)
        red[(lane + 32 * j) * 8 + w] = make_float2(best[j], __int_as_float(bidx[j]));
    __syncthreads();

    {
        float bs = 3.402823466e38f;
        int   bi = 0x7fffffff;
        #pragma unroll
        for (int t = 0; t < 8; t++) {
            float2 p = red[tid * 8 + t];
            int ix = __float_as_int(p.y);
            if (p.x < bs || (p.x == bs && ix < bi)) { bs = p.x; bi = ix; }
        }
        int row = rowBase + tid;
        if (row < n_rows) out[row] = (float)bi;
    }
}

extern "C" void kernel_launch(void* const* d_in, const int* in_sizes, int n_in,
                              void* d_out, int out_size)
{
    // Inputs by size: latent (131072x128) larger than coords (2048x128).
    int i_lat = 0, i_crd = 1;
    if (n_in >= 2 && in_sizes[1] > in_sizes[0]) { i_lat = 1; i_crd = 0; }

    const float* latent = (const float*)d_in[i_lat];
    const float* coords = (const float*)d_in[i_crd];

    int n_rows_a = out_size;
    int n_rows_b = in_sizes[i_lat] / DIM;
    int n_rows = n_rows_a < n_rows_b ? n_rows_a : n_rows_b;
    int n_cent = in_sizes[i_crd] / DIM;       // 2048
    float* out = (float*)d_out;

    size_t smem = SMEM_FLOATS * sizeof(float);   // ~202 KB

    static bool attr_set = false;
    if (!attr_set) {
        cudaFuncSetAttribute(centroids_argmin_kernel,
                             cudaFuncAttributeMaxDynamicSharedMemorySize,
                             (int)smem);
        attr_set = true;
    }

    c2_kernel<<<(n_cent + 7) / 8, 256>>>(coords, n_cent);

    dim3 grid((n_rows + CTA_M - 1) / CTA_M);
    centroids_argmin_kernel<<<grid, THREADS, smem>>>(latent, coords, out,
                                                     n_rows, n_cent);
}

// round 11
// speedup vs baseline: 1.4200x; 1.1084x over previous
#include <cuda_runtime.h>
#include <cstdint>

// Centroids: out[n] = argmin_c ( |c|^2 - 2 * latent[n].coords[c] )
// 8x8 register micro-tile, mixed smem addressing:
//   lanes -> rows   (A LDS.128 distinct, conflict-free via 132-stride pad)
//   warps -> cents  (B LDS.128 warp-uniform broadcast)
// R11: per-kq operands fully staged up-front (a[8]+b[8], MLP=16) and kq loop
// kept small (unroll 1) so ptxas can pipeline loads across the back-edge.
// Output: float32 indices (established R6).

#define THREADS  256
#define CTA_M    256
#define TILE_N   64
#define DIM      128
#define AS       132              // padded A stride (floats)
#define BS       132              // padded B stride (floats)

#define SM_A     0                           // 256*132 floats
#define SM_B(b)  (CTA_M * AS + (b) * TILE_N * BS)
#define SM_C2(b) (CTA_M * AS + 2 * TILE_N * BS + (b) * TILE_N)
#define SM_RED   SM_B(0)                     // reuse B for final reduce
#define SMEM_FLOATS (CTA_M * AS + 2 * TILE_N * BS + 2 * TILE_N)

__device__ float g_c2[4096];   // |c|^2 per centroid

__device__ __forceinline__ unsigned long long ffma2(unsigned long long a,
                                                    unsigned long long b,
                                                    unsigned long long c) {
    unsigned long long d;
    asm("fma.rn.f32x2 %0, %1, %2, %3;" : "=l"(d) : "l"(a), "l"(b), "l"(c));
    return d;
}
__device__ __forceinline__ float2 unpack_f32x2(unsigned long long v) {
    float2 f;
    asm("mov.b64 {%0, %1}, %2;" : "=f"(f.x), "=f"(f.y) : "l"(v));
    return f;
}

// ---- pass 1: |c|^2, one warp per centroid ----
__global__ void c2_kernel(const float* __restrict__ coords, int n_cent) {
    int c    = blockIdx.x * 8 + (threadIdx.x >> 5);
    int lane = threadIdx.x & 31;
    if (c >= n_cent) return;
    const float4* p = reinterpret_cast<const float4*>(coords + (size_t)c * DIM);
    float4 v = p[lane];
    float s = v.x * v.x + v.y * v.y + v.z * v.z + v.w * v.w;
    #pragma unroll
    for (int off = 16; off > 0; off >>= 1)
        s += __shfl_xor_sync(0xffffffffu, s, off);
    if (lane == 0) g_c2[c] = s;
}

// ---- pass 2: 8x8 micro-tile FFMA2 GEMM + argmin ----
__global__ void __launch_bounds__(THREADS, 1)
centroids_argmin_kernel(const float* __restrict__ latent,
                        const float* __restrict__ coords,
                        float* __restrict__ out,
                        int n_rows, int n_cent)
{
    extern __shared__ float sm[];

    const int tid  = threadIdx.x;
    const int lane = tid & 31;
    const int w    = tid >> 5;          // warp 0..7 -> centroid slice
    const int rowBase = blockIdx.x * CTA_M;
    const int n_tiles = n_cent / TILE_N;

    // ---- A tile: 256 rows x 128 k (padded stride) ----
    {
        const float4* g = reinterpret_cast<const float4*>(latent);
        #pragma unroll
        for (int t = tid; t < CTA_M * 32; t += THREADS) {
            int r  = t >> 5;
            int kq = t & 31;
            int gr = rowBase + r; if (gr >= n_rows) gr = n_rows - 1;
            *reinterpret_cast<float4*>(sm + SM_A + r * AS + kq * 4) =
                g[(size_t)gr * 32 + kq];
        }
    }

    const float4* crd4 = reinterpret_cast<const float4*>(coords);
    auto loadB = [&](int nbt) {
        int buf = nbt & 1;
        #pragma unroll
        for (int t = tid; t < TILE_N * 32; t += THREADS) {
            int r  = t >> 5;
            int kq = t & 31;
            int gc = nbt * TILE_N + r; if (gc >= n_cent) gc = n_cent - 1;
            *reinterpret_cast<float4*>(sm + SM_B(buf) + r * BS + kq * 4) =
                crd4[(size_t)gc * 32 + kq];
        }
        if (tid < TILE_N) {
            int gc = nbt * TILE_N + tid; if (gc >= n_cent) gc = n_cent - 1;
            sm[SM_C2(buf) + tid] = g_c2[gc];
        }
    };

    float best[8];
    int   bidx[8];
    #pragma unroll
    for (int j = 0; j < 8; j++) { best[j] = 3.402823466e38f; bidx[j] = 0; }

    loadB(0);
    __syncthreads();

    for (int nb = 0; nb < n_tiles; nb++) {
        int cur = nb & 1;
        if (nb + 1 < n_tiles) loadB(nb + 1);

        const float* Bb = sm + SM_B(cur) + (w * 8) * BS;
        const float* Ab = sm + SM_A + lane * AS;

        unsigned long long acc[8][8];
        #pragma unroll
        for (int j = 0; j < 8; j++)
            #pragma unroll
            for (int i = 0; i < 8; i++) acc[j][i] = 0ull;

        #pragma unroll 1
        for (int kq = 0; kq < 32; kq++) {
            // Stage ALL operands for this kq first: 16 back-to-back LDS.128
            // (MLP=16), then a pure FFMA2 burst — schedulable with reg slack.
            ulonglong2 a[8], b[8];
            #pragma unroll
            for (int j = 0; j < 8; j++)      // lane-distinct rows
                a[j] = *reinterpret_cast<const ulonglong2*>(
                           Ab + (32 * j) * AS + kq * 4);
            #pragma unroll
            for (int i = 0; i < 8; i++)      // warp-uniform -> broadcast
                b[i] = *reinterpret_cast<const ulonglong2*>(Bb + i * BS + kq * 4);
            #pragma unroll
            for (int j = 0; j < 8; j++)
                #pragma unroll
                for (int i = 0; i < 8; i++)
                    acc[j][i] = ffma2(a[j].y, b[i].y,
                                      ffma2(a[j].x, b[i].x, acc[j][i]));
        }

        // Fold + running argmin for this thread's 8 rows x 8 cents.
        const float* c2s = sm + SM_C2(cur) + w * 8;
        #pragma unroll
        for (int j = 0; j < 8; j++)
            #pragma unroll
            for (int i = 0; i < 8; i++) {
                float2 f = unpack_f32x2(acc[j][i]);
                float score = fmaf(-2.0f, f.x + f.y, c2s[i]);
                if (score < best[j]) { best[j] = score; bidx[j] = nb * TILE_N + w * 8 + i; }
            }

        __syncthreads();   // compute done + next-B loaded before buffer reuse
    }

    // ---- cross-warp reduction: row (lane+32j) best over 8 warps ----
    float2* red = reinterpret_cast<float2*>(sm + SM_RED);   // [256][8]
    #pragma unroll
    for (int j = 0; j < 8; j++)
        red[(lane + 32 * j) * 8 + w] = make_float2(best[j], __int_as_float(bidx[j]));
    __syncthreads();

    {
        float bs = 3.402823466e38f;
        int   bi = 0x7fffffff;
        #pragma unroll
        for (int t = 0; t < 8; t++) {
            float2 p = red[tid * 8 + t];
            int ix = __float_as_int(p.y);
            if (p.x < bs || (p.x == bs && ix < bi)) { bs = p.x; bi = ix; }
        }
        int row = rowBase + tid;
        if (row < n_rows) out[row] = (float)bi;
    }
}

extern "C" void kernel_launch(void* const* d_in, const int* in_sizes, int n_in,
                              void* d_out, int out_size)
{
    // Inputs by size: latent (131072x128) larger than coords (2048x128).
    int i_lat = 0, i_crd = 1;
    if (n_in >= 2 && in_sizes[1] > in_sizes[0]) { i_lat = 1; i_crd = 0; }

    const float* latent = (const float*)d_in[i_lat];
    const float* coords = (const float*)d_in[i_crd];

    int n_rows_a = out_size;
    int n_rows_b = in_sizes[i_lat] / DIM;
    int n_rows = n_rows_a < n_rows_b ? n_rows_a : n_rows_b;
    int n_cent = in_sizes[i_crd] / DIM;       // 2048
    float* out = (float*)d_out;

    size_t smem = SMEM_FLOATS * sizeof(float);   // ~202 KB

    static bool attr_set = false;
    if (!attr_set) {
        cudaFuncSetAttribute(centroids_argmin_kernel,
                             cudaFuncAttributeMaxDynamicSharedMemorySize,
                             (int)smem);
        attr_set = true;
    }

    c2_kernel<<<(n_cent + 7) / 8, 256>>>(coords, n_cent);

    dim3 grid((n_rows + CTA_M - 1) / CTA_M);
    centroids_argmin_kernel<<<grid, THREADS, smem>>>(latent, coords, out,
                                                     n_rows, n_cent);
}

// round 13
// speedup vs baseline: 1.9237x; 1.3547x over previous
#include <cuda_runtime.h>
#include <cstdint>

// Centroids argmin via legacy mma.sync 3xTF32 split (fp32-grade accuracy).
// score[n,c] = |c|^2 - 2*(latent[n].coords[c]);  out[n] = argmin_c (float)
// dot = Ahi*Bhi + Ahi*Blo + Alo*Bhi  (tf32 mma, fp32 accumulate)
// CTA: 128 rows x 64 cents, 8 warps (4M x 2N), warp tile 32x32, K=128.
// R13 fix: cross-warpN reduction (R12 raced two half-column argmins).

#define DIM      128
#define CTA_M    128
#define TILE_N   64
#define THREADS  256
#define PS       132                    // padded smem stride (floats)

// smem float offsets
#define SA_HI 0
#define SA_LO (CTA_M * PS)              // 16896
#define SB_HI (2 * CTA_M * PS)          // 33792
#define SB_LO (2 * CTA_M * PS + TILE_N * PS)
#define S_C2  (2 * CTA_M * PS + 2 * TILE_N * PS)
#define SMEM_FLOATS (S_C2 + TILE_N)

__device__ float g_c2[2048];
__device__ float g_bhi[2048 * DIM];     // coords tf32-hi (1 MB)
__device__ float g_blo[2048 * DIM];     // coords tf32-lo (1 MB)

__device__ __forceinline__ uint32_t tf32_rna(float x) {
    uint32_t u;
    asm("cvt.rna.tf32.f32 %0, %1;" : "=r"(u) : "f"(x));
    return u;
}
__device__ __forceinline__ void tf32_split(float x, float& hi, float& lo) {
    uint32_t h = tf32_rna(x);
    hi = __uint_as_float(h);
    lo = __uint_as_float(tf32_rna(x - hi));
}
__device__ __forceinline__ void mma_tf32(float* c, const uint32_t* a,
                                         const uint32_t* b) {
    asm volatile(
        "mma.sync.aligned.m16n8k8.row.col.f32.tf32.tf32.f32 "
        "{%0,%1,%2,%3}, {%4,%5,%6,%7}, {%8,%9}, {%0,%1,%2,%3};"
        : "+f"(c[0]), "+f"(c[1]), "+f"(c[2]), "+f"(c[3])
        : "r"(a[0]), "r"(a[1]), "r"(a[2]), "r"(a[3]), "r"(b[0]), "r"(b[1]));
}

// ---- prep: per-centroid |c|^2 + tf32 hi/lo split (warp per centroid) ----
__global__ void prep_kernel(const float* __restrict__ coords, int n_cent) {
    int c    = blockIdx.x * 8 + (threadIdx.x >> 5);
    int lane = threadIdx.x & 31;
    if (c >= n_cent) return;
    const float4* p = reinterpret_cast<const float4*>(coords + (size_t)c * DIM);
    float4 v = p[lane];
    float s = v.x * v.x + v.y * v.y + v.z * v.z + v.w * v.w;
    #pragma unroll
    for (int off = 16; off > 0; off >>= 1)
        s += __shfl_xor_sync(0xffffffffu, s, off);
    if (lane == 0) g_c2[c] = s;

    float4 hi, lo;
    tf32_split(v.x, hi.x, lo.x);
    tf32_split(v.y, hi.y, lo.y);
    tf32_split(v.z, hi.z, lo.z);
    tf32_split(v.w, hi.w, lo.w);
    reinterpret_cast<float4*>(g_bhi + (size_t)c * DIM)[lane] = hi;
    reinterpret_cast<float4*>(g_blo + (size_t)c * DIM)[lane] = lo;
}

// ---- main: 3xTF32 mma GEMM + running argmin ----
__global__ void __launch_bounds__(THREADS, 1)
centroids_mma_kernel(const float* __restrict__ latent,
                     float* __restrict__ out,
                     int n_rows, int n_cent)
{
    extern __shared__ float sm[];

    const int tid   = threadIdx.x;
    const int lane  = tid & 31;
    const int w     = tid >> 5;
    const int warpM = w >> 1;            // 0..3
    const int warpN = w & 1;             // 0..1
    const int g     = lane >> 2;         // group 0..7
    const int t     = lane & 3;          // thread-in-group 0..3
    const int rowBase = blockIdx.x * CTA_M;
    const int n_tiles = n_cent / TILE_N;

    // ---- A tile: load + split 128 rows x 128 k ----
    {
        const float4* g4 = reinterpret_cast<const float4*>(latent);
        for (int it = tid; it < CTA_M * 32; it += THREADS) {
            int r  = it >> 5;
            int kq = it & 31;
            int gr = rowBase + r; if (gr >= n_rows) gr = n_rows - 1;
            float4 v = g4[(size_t)gr * 32 + kq];
            float4 hi, lo;
            tf32_split(v.x, hi.x, lo.x);
            tf32_split(v.y, hi.y, lo.y);
            tf32_split(v.z, hi.z, lo.z);
            tf32_split(v.w, hi.w, lo.w);
            *reinterpret_cast<float4*>(sm + SA_HI + r * PS + kq * 4) = hi;
            *reinterpret_cast<float4*>(sm + SA_LO + r * PS + kq * 4) = lo;
        }
    }

    // per-lane running argmin: [mfrag][rowslot] (rows g, g+8)
    float best[2][2];
    int   bidx[2][2];
    #pragma unroll
    for (int mf = 0; mf < 2; mf++)
        #pragma unroll
        for (int rs = 0; rs < 2; rs++) { best[mf][rs] = 3.402823466e38f; bidx[mf][rs] = 0; }

    const int aRow0 = warpM * 32 + g;          // + mf*16 (+8 for upper slot)
    const int bCol0 = warpN * 32 + g;          // + nf*8

    for (int nb = 0; nb < n_tiles; nb++) {
        __syncthreads();   // previous tile's reads complete
        // ---- B tile: 64 cents, pre-split ----
        {
            const float4* bh = reinterpret_cast<const float4*>(g_bhi);
            const float4* bl = reinterpret_cast<const float4*>(g_blo);
            for (int it = tid; it < TILE_N * 32; it += THREADS) {
                int r  = it >> 5;
                int kq = it & 31;
                size_t src = (size_t)(nb * TILE_N + r) * 32 + kq;
                *reinterpret_cast<float4*>(sm + SB_HI + r * PS + kq * 4) = bh[src];
                *reinterpret_cast<float4*>(sm + SB_LO + r * PS + kq * 4) = bl[src];
            }
            if (tid < TILE_N) sm[S_C2 + tid] = g_c2[nb * TILE_N + tid];
        }
        __syncthreads();

        float acc[2][4][4];
        #pragma unroll
        for (int mf = 0; mf < 2; mf++)
            #pragma unroll
            for (int nf = 0; nf < 4; nf++)
                #pragma unroll
                for (int q = 0; q < 4; q++) acc[mf][nf][q] = 0.0f;

        #pragma unroll 4
        for (int ks = 0; ks < 16; ks++) {
            const int k0 = ks * 8;
            uint32_t ahi[2][4], alo[2][4], bhi[4][2], blo[4][2];
            #pragma unroll
            for (int mf = 0; mf < 2; mf++) {
                int r0 = (aRow0 + mf * 16) * PS + k0 + t;
                int r1 = r0 + 8 * PS;
                ahi[mf][0] = __float_as_uint(sm[SA_HI + r0]);
                ahi[mf][1] = __float_as_uint(sm[SA_HI + r1]);
                ahi[mf][2] = __float_as_uint(sm[SA_HI + r0 + 4]);
                ahi[mf][3] = __float_as_uint(sm[SA_HI + r1 + 4]);
                alo[mf][0] = __float_as_uint(sm[SA_LO + r0]);
                alo[mf][1] = __float_as_uint(sm[SA_LO + r1]);
                alo[mf][2] = __float_as_uint(sm[SA_LO + r0 + 4]);
                alo[mf][3] = __float_as_uint(sm[SA_LO + r1 + 4]);
            }
            #pragma unroll
            for (int nf = 0; nf < 4; nf++) {
                int n0 = (bCol0 + nf * 8) * PS + k0 + t;
                bhi[nf][0] = __float_as_uint(sm[SB_HI + n0]);
                bhi[nf][1] = __float_as_uint(sm[SB_HI + n0 + 4]);
                blo[nf][0] = __float_as_uint(sm[SB_LO + n0]);
                blo[nf][1] = __float_as_uint(sm[SB_LO + n0 + 4]);
            }
            #pragma unroll
            for (int mf = 0; mf < 2; mf++)
                #pragma unroll
                for (int nf = 0; nf < 4; nf++) {
                    mma_tf32(acc[mf][nf], ahi[mf], bhi[nf]);
                    mma_tf32(acc[mf][nf], ahi[mf], blo[nf]);
                    mma_tf32(acc[mf][nf], alo[mf], bhi[nf]);
                }
        }

        // ---- tile epilogue: scores + running argmin ----
        #pragma unroll
        for (int nf = 0; nf < 4; nf++) {
            int cl = warpN * 32 + nf * 8 + 2 * t;          // local col
            float2 cc = *reinterpret_cast<const float2*>(sm + S_C2 + cl);
            int c0 = nb * TILE_N + cl;
            #pragma unroll
            for (int mf = 0; mf < 2; mf++) {
                float s0 = fmaf(-2.0f, acc[mf][nf][0], cc.x);
                float s1 = fmaf(-2.0f, acc[mf][nf][1], cc.y);
                float s2 = fmaf(-2.0f, acc[mf][nf][2], cc.x);
                float s3 = fmaf(-2.0f, acc[mf][nf][3], cc.y);
                if (s0 < best[mf][0]) { best[mf][0] = s0; bidx[mf][0] = c0; }
                if (s1 < best[mf][0]) { best[mf][0] = s1; bidx[mf][0] = c0 + 1; }
                if (s2 < best[mf][1]) { best[mf][1] = s2; bidx[mf][1] = c0; }
                if (s3 < best[mf][1]) { best[mf][1] = s3; bidx[mf][1] = c0 + 1; }
            }
        }
    }

    // ---- reduce across the 4 t-lanes of each group ----
    #pragma unroll
    for (int mf = 0; mf < 2; mf++)
        #pragma unroll
        for (int rs = 0; rs < 2; rs++) {
            float s = best[mf][rs];
            int   i = bidx[mf][rs];
            #pragma unroll
            for (int off = 1; off <= 2; off <<= 1) {
                float os = __shfl_xor_sync(0xffffffffu, s, off);
                int   oi = __shfl_xor_sync(0xffffffffu, i, off);
                if (os < s || (os == s && oi < i)) { s = os; i = oi; }
            }
            best[mf][rs] = s;
            bidx[mf][rs] = i;
        }

    // ---- R13: cross-warpN reduction via smem (both N-warps own same rows) ----
    __syncthreads();                       // all tile reads done; reuse smem
    float2* red = reinterpret_cast<float2*>(sm);   // [CTA_M][2]
    if (t == 0) {
        #pragma unroll
        for (int mf = 0; mf < 2; mf++)
            #pragma unroll
            for (int rs = 0; rs < 2; rs++) {
                int rl = warpM * 32 + mf * 16 + rs * 8 + g;
                red[rl * 2 + warpN] =
                    make_float2(best[mf][rs], __int_as_float(bidx[mf][rs]));
            }
    }
    __syncthreads();
    if (tid < CTA_M) {
        float2 p0 = red[tid * 2 + 0];
        float2 p1 = red[tid * 2 + 1];
        int   i0 = __float_as_int(p0.y);
        int   i1 = __float_as_int(p1.y);
        int   bi = (p1.x < p0.x || (p1.x == p0.x && i1 < i0)) ? i1 : i0;
        int row = rowBase + tid;
        if (row < n_rows) out[row] = (float)bi;
    }
}

extern "C" void kernel_launch(void* const* d_in, const int* in_sizes, int n_in,
                              void* d_out, int out_size)
{
    // Inputs by size: latent (131072x128) larger than coords (2048x128).
    int i_lat = 0, i_crd = 1;
    if (n_in >= 2 && in_sizes[1] > in_sizes[0]) { i_lat = 1; i_crd = 0; }

    const float* latent = (const float*)d_in[i_lat];
    const float* coords = (const float*)d_in[i_crd];

    int n_rows_a = out_size;
    int n_rows_b = in_sizes[i_lat] / DIM;
    int n_rows = n_rows_a < n_rows_b ? n_rows_a : n_rows_b;
    int n_cent = in_sizes[i_crd] / DIM;       // 2048
    float* out = (float*)d_out;

    size_t smem = SMEM_FLOATS * sizeof(float);   // ~203 KB

    static bool attr_set = false;
    if (!attr_set) {
        cudaFuncSetAttribute(centroids_mma_kernel,
                             cudaFuncAttributeMaxDynamicSharedMemorySize,
                             (int)smem);
        attr_set = true;
    }

    prep_kernel<<<(n_cent + 7) / 8, 256>>>(coords, n_cent);

    dim3 grid((n_rows + CTA_M - 1) / CTA_M);
    centroids_mma_kernel<<<grid, THREADS, smem>>>(latent, out, n_rows, n_cent);
}

// round 15
// speedup vs baseline: 2.0864x; 1.0846x over previous
#include <cuda_runtime.h>
#include <cstdint>

// Centroids argmin via legacy mma.sync 3xTF32 split (fp32-grade accuracy).
// score[n,c] = |c|^2 - 2*(latent[n].coords[c]);  out[n] = argmin_c (float)
// dot = Ahi*Bhi + Ahi*Blo + Alo*Bhi  (tf32 mma, fp32 accumulate)
// CTA: 128 rows x 64 cents, 8 warps (4M x 2N), warp tile 32x32, K=128.
// R15: fix R14 prefetch coverage (8 float4/thread/array, rows 0..63) —
//      R14 only wrote rows 0..31, leaving stale B data in rows 32..63.

#define DIM      128
#define CTA_M    128
#define TILE_N   64
#define THREADS  256
#define PS       132                    // padded smem stride (floats)

// smem float offsets
#define SA_HI 0
#define SA_LO (CTA_M * PS)
#define SB_HI (2 * CTA_M * PS)
#define SB_LO (2 * CTA_M * PS + TILE_N * PS)
#define S_C2  (2 * CTA_M * PS + 2 * TILE_N * PS)
#define SMEM_FLOATS (S_C2 + TILE_N)

__device__ float g_c2[2048];
__device__ float g_bhi[2048 * DIM];     // coords tf32-hi (1 MB)
__device__ float g_blo[2048 * DIM];     // coords tf32-lo (1 MB)

__device__ __forceinline__ uint32_t tf32_rna(float x) {
    uint32_t u;
    asm("cvt.rna.tf32.f32 %0, %1;" : "=r"(u) : "f"(x));
    return u;
}
__device__ __forceinline__ void tf32_split(float x, float& hi, float& lo) {
    uint32_t h = tf32_rna(x);
    hi = __uint_as_float(h);
    lo = __uint_as_float(tf32_rna(x - hi));
}
__device__ __forceinline__ void mma_tf32(float* c, const uint32_t* a,
                                         const uint32_t* b) {
    asm volatile(
        "mma.sync.aligned.m16n8k8.row.col.f32.tf32.tf32.f32 "
        "{%0,%1,%2,%3}, {%4,%5,%6,%7}, {%8,%9}, {%0,%1,%2,%3};"
        : "+f"(c[0]), "+f"(c[1]), "+f"(c[2]), "+f"(c[3])
        : "r"(a[0]), "r"(a[1]), "r"(a[2]), "r"(a[3]), "r"(b[0]), "r"(b[1]));
}

// ---- prep: per-centroid |c|^2 + tf32 hi/lo split (warp per centroid) ----
__global__ void prep_kernel(const float* __restrict__ coords, int n_cent) {
    int c    = blockIdx.x * 8 + (threadIdx.x >> 5);
    int lane = threadIdx.x & 31;
    if (c >= n_cent) return;
    const float4* p = reinterpret_cast<const float4*>(coords + (size_t)c * DIM);
    float4 v = p[lane];
    float s = v.x * v.x + v.y * v.y + v.z * v.z + v.w * v.w;
    #pragma unroll
    for (int off = 16; off > 0; off >>= 1)
        s += __shfl_xor_sync(0xffffffffu, s, off);
    if (lane == 0) g_c2[c] = s;

    float4 hi, lo;
    tf32_split(v.x, hi.x, lo.x);
    tf32_split(v.y, hi.y, lo.y);
    tf32_split(v.z, hi.z, lo.z);
    tf32_split(v.w, hi.w, lo.w);
    reinterpret_cast<float4*>(g_bhi + (size_t)c * DIM)[lane] = hi;
    reinterpret_cast<float4*>(g_blo + (size_t)c * DIM)[lane] = lo;
}

// ---- main: 3xTF32 mma GEMM + running argmin ----
__global__ void __launch_bounds__(THREADS, 1)
centroids_mma_kernel(const float* __restrict__ latent,
                     float* __restrict__ out,
                     int n_rows, int n_cent)
{
    extern __shared__ float sm[];

    const int tid   = threadIdx.x;
    const int lane  = tid & 31;
    const int w     = tid >> 5;
    const int warpM = w >> 1;            // 0..3
    const int warpN = w & 1;             // 0..1
    const int g     = lane >> 2;         // group 0..7
    const int t     = lane & 3;          // thread-in-group 0..3
    const int rowBase = blockIdx.x * CTA_M;
    const int n_tiles = n_cent / TILE_N;

    // ---- A tile: load + split 128 rows x 128 k ----
    {
        const float4* g4 = reinterpret_cast<const float4*>(latent);
        for (int it = tid; it < CTA_M * 32; it += THREADS) {
            int r  = it >> 5;
            int kq = it & 31;
            int gr = rowBase + r; if (gr >= n_rows) gr = n_rows - 1;
            float4 v = g4[(size_t)gr * 32 + kq];
            float4 hi, lo;
            tf32_split(v.x, hi.x, lo.x);
            tf32_split(v.y, hi.y, lo.y);
            tf32_split(v.z, hi.z, lo.z);
            tf32_split(v.w, hi.w, lo.w);
            *reinterpret_cast<float4*>(sm + SA_HI + r * PS + kq * 4) = hi;
            *reinterpret_cast<float4*>(sm + SA_LO + r * PS + kq * 4) = lo;
        }
    }

    // ---- B tile 0 directly to smem ----
    {
        const float4* bh = reinterpret_cast<const float4*>(g_bhi);
        const float4* bl = reinterpret_cast<const float4*>(g_blo);
        for (int it = tid; it < TILE_N * 32; it += THREADS) {
            int r  = it >> 5;
            int kq = it & 31;
            *reinterpret_cast<float4*>(sm + SB_HI + r * PS + kq * 4) = bh[(size_t)r * 32 + kq];
            *reinterpret_cast<float4*>(sm + SB_LO + r * PS + kq * 4) = bl[(size_t)r * 32 + kq];
        }
        if (tid < TILE_N) sm[S_C2 + tid] = g_c2[tid];
    }
    __syncthreads();

    // per-lane running argmin: [mfrag][rowslot] (rows g, g+8)
    float best[2][2];
    int   bidx[2][2];
    #pragma unroll
    for (int mf = 0; mf < 2; mf++)
        #pragma unroll
        for (int rs = 0; rs < 2; rs++) { best[mf][rs] = 3.402823466e38f; bidx[mf][rs] = 0; }

    const int aRow0 = warpM * 32 + g;
    const int bCol0 = warpN * 32 + g;
    const int pfR   = tid >> 5;          // prefetch base row (0..7)
    const int pfK   = tid & 31;          // prefetch kq slot

    const float4* bh4 = reinterpret_cast<const float4*>(g_bhi);
    const float4* bl4 = reinterpret_cast<const float4*>(g_blo);

    for (int nb = 0; nb < n_tiles; nb++) {
        // ---- prefetch next B tile into registers (hidden under compute) ----
        // 8 float4 per array per thread: rows pfR + 8p, p=0..7 -> rows 0..63.
        float4 pf_hi[8], pf_lo[8];
        float  pf_c2 = 0.0f;
        if (nb + 1 < n_tiles) {
            #pragma unroll
            for (int p = 0; p < 8; p++) {
                size_t src = (size_t)((nb + 1) * TILE_N + pfR + p * 8) * 32 + pfK;
                pf_hi[p] = bh4[src];
                pf_lo[p] = bl4[src];
            }
            if (tid < TILE_N) pf_c2 = g_c2[(nb + 1) * TILE_N + tid];
        }

        // ---- compute current tile: 3 independent accumulator banks ----
        float acc[3][2][4][4];
        #pragma unroll
        for (int s = 0; s < 3; s++)
            #pragma unroll
            for (int mf = 0; mf < 2; mf++)
                #pragma unroll
                for (int nf = 0; nf < 4; nf++)
                    #pragma unroll
                    for (int q = 0; q < 4; q++) acc[s][mf][nf][q] = 0.0f;

        #pragma unroll 2
        for (int ks = 0; ks < 16; ks++) {
            const int k0 = ks * 8;
            uint32_t ahi[2][4], alo[2][4], bhi[4][2], blo[4][2];
            #pragma unroll
            for (int mf = 0; mf < 2; mf++) {
                int r0 = (aRow0 + mf * 16) * PS + k0 + t;
                int r1 = r0 + 8 * PS;
                ahi[mf][0] = __float_as_uint(sm[SA_HI + r0]);
                ahi[mf][1] = __float_as_uint(sm[SA_HI + r1]);
                ahi[mf][2] = __float_as_uint(sm[SA_HI + r0 + 4]);
                ahi[mf][3] = __float_as_uint(sm[SA_HI + r1 + 4]);
                alo[mf][0] = __float_as_uint(sm[SA_LO + r0]);
                alo[mf][1] = __float_as_uint(sm[SA_LO + r1]);
                alo[mf][2] = __float_as_uint(sm[SA_LO + r0 + 4]);
                alo[mf][3] = __float_as_uint(sm[SA_LO + r1 + 4]);
            }
            #pragma unroll
            for (int nf = 0; nf < 4; nf++) {
                int n0 = (bCol0 + nf * 8) * PS + k0 + t;
                bhi[nf][0] = __float_as_uint(sm[SB_HI + n0]);
                bhi[nf][1] = __float_as_uint(sm[SB_HI + n0 + 4]);
                blo[nf][0] = __float_as_uint(sm[SB_LO + n0]);
                blo[nf][1] = __float_as_uint(sm[SB_LO + n0 + 4]);
            }
            // 24 fully independent MMAs (separate acc banks)
            #pragma unroll
            for (int mf = 0; mf < 2; mf++)
                #pragma unroll
                for (int nf = 0; nf < 4; nf++)
                    mma_tf32(acc[0][mf][nf], ahi[mf], bhi[nf]);
            #pragma unroll
            for (int mf = 0; mf < 2; mf++)
                #pragma unroll
                for (int nf = 0; nf < 4; nf++)
                    mma_tf32(acc[1][mf][nf], ahi[mf], blo[nf]);
            #pragma unroll
            for (int mf = 0; mf < 2; mf++)
                #pragma unroll
                for (int nf = 0; nf < 4; nf++)
                    mma_tf32(acc[2][mf][nf], alo[mf], bhi[nf]);
        }

        // ---- tile epilogue: fold banks, scores, running argmin ----
        #pragma unroll
        for (int nf = 0; nf < 4; nf++) {
            int cl = warpN * 32 + nf * 8 + 2 * t;
            float2 cc = *reinterpret_cast<const float2*>(sm + S_C2 + cl);
            int c0 = nb * TILE_N + cl;
            #pragma unroll
            for (int mf = 0; mf < 2; mf++) {
                float d0 = acc[0][mf][nf][0] + acc[1][mf][nf][0] + acc[2][mf][nf][0];
                float d1 = acc[0][mf][nf][1] + acc[1][mf][nf][1] + acc[2][mf][nf][1];
                float d2 = acc[0][mf][nf][2] + acc[1][mf][nf][2] + acc[2][mf][nf][2];
                float d3 = acc[0][mf][nf][3] + acc[1][mf][nf][3] + acc[2][mf][nf][3];
                float s0 = fmaf(-2.0f, d0, cc.x);
                float s1 = fmaf(-2.0f, d1, cc.y);
                float s2 = fmaf(-2.0f, d2, cc.x);
                float s3 = fmaf(-2.0f, d3, cc.y);
                if (s0 < best[mf][0]) { best[mf][0] = s0; bidx[mf][0] = c0; }
                if (s1 < best[mf][0]) { best[mf][0] = s1; bidx[mf][0] = c0 + 1; }
                if (s2 < best[mf][1]) { best[mf][1] = s2; bidx[mf][1] = c0; }
                if (s3 < best[mf][1]) { best[mf][1] = s3; bidx[mf][1] = c0 + 1; }
            }
        }

        __syncthreads();   // all reads of tile nb complete

        // ---- commit prefetched B tile to smem (full 64 rows) ----
        if (nb + 1 < n_tiles) {
            #pragma unroll
            for (int p = 0; p < 8; p++) {
                int r = pfR + p * 8;
                *reinterpret_cast<float4*>(sm + SB_HI + r * PS + pfK * 4) = pf_hi[p];
                *reinterpret_cast<float4*>(sm + SB_LO + r * PS + pfK * 4) = pf_lo[p];
            }
            if (tid < TILE_N) sm[S_C2 + tid] = pf_c2;
            __syncthreads();
        }
    }

    // ---- reduce across the 4 t-lanes of each group ----
    #pragma unroll
    for (int mf = 0; mf < 2; mf++)
        #pragma unroll
        for (int rs = 0; rs < 2; rs++) {
            float s = best[mf][rs];
            int   i = bidx[mf][rs];
            #pragma unroll
            for (int off = 1; off <= 2; off <<= 1) {
                float os = __shfl_xor_sync(0xffffffffu, s, off);
                int   oi = __shfl_xor_sync(0xffffffffu, i, off);
                if (os < s || (os == s && oi < i)) { s = os; i = oi; }
            }
            best[mf][rs] = s;
            bidx[mf][rs] = i;
        }

    // ---- cross-warpN reduction via smem ----
    __syncthreads();
    float2* red = reinterpret_cast<float2*>(sm);   // [CTA_M][2]
    if (t == 0) {
        #pragma unroll
        for (int mf = 0; mf < 2; mf++)
            #pragma unroll
            for (int rs = 0; rs < 2; rs++) {
                int rl = warpM * 32 + mf * 16 + rs * 8 + g;
                red[rl * 2 + warpN] =
                    make_float2(best[mf][rs], __int_as_float(bidx[mf][rs]));
            }
    }
    __syncthreads();
    if (tid < CTA_M) {
        float2 p0 = red[tid * 2 + 0];
        float2 p1 = red[tid * 2 + 1];
        int   i0 = __float_as_int(p0.y);
        int   i1 = __float_as_int(p1.y);
        int   bi = (p1.x < p0.x || (p1.x == p0.x && i1 < i0)) ? i1 : i0;
        int row = rowBase + tid;
        if (row < n_rows) out[row] = (float)bi;
    }
}

extern "C" void kernel_launch(void* const* d_in, const int* in_sizes, int n_in,
                              void* d_out, int out_size)
{
    // Inputs by size: latent (131072x128) larger than coords (2048x128).
    int i_lat = 0, i_crd = 1;
    if (n_in >= 2 && in_sizes[1] > in_sizes[0]) { i_lat = 1; i_crd = 0; }

    const float* latent = (const float*)d_in[i_lat];
    const float* coords = (const float*)d_in[i_crd];

    int n_rows_a = out_size;
    int n_rows_b = in_sizes[i_lat] / DIM;
    int n_rows = n_rows_a < n_rows_b ? n_rows_a : n_rows_b;
    int n_cent = in_sizes[i_crd] / DIM;       // 2048
    float* out = (float*)d_out;

    size_t smem = SMEM_FLOATS * sizeof(float);   // ~203 KB

    static bool attr_set = false;
    if (!attr_set) {
        cudaFuncSetAttribute(centroids_mma_kernel,
                             cudaFuncAttributeMaxDynamicSharedMemorySize,
                             (int)smem);
        attr_set = true;
    }

    prep_kernel<<<(n_cent + 7) / 8, 256>>>(coords, n_cent);

    dim3 grid((n_rows + CTA_M - 1) / CTA_M);
    centroids_mma_kernel<<<grid, THREADS, smem>>>(latent, out, n_rows, n_cent);
}